// round 1
// baseline (speedup 1.0000x reference)
#include <cuda_runtime.h>
#include <cuda_bf16.h>
#include <cstdint>

#define B_   32
#define S_   512
#define D_   768
#define EPS_ 1e-8f

// ---------------- device scratch (no allocations allowed) ----------------
__device__ __nv_bfloat16 g_n1[B_ * S_ * D_];
__device__ __nv_bfloat16 g_n2[B_ * S_ * D_];
__device__ float g_rowmax[B_ * S_];
__device__ float g_colmax[B_ * S_];

// ---------------- helpers ----------------
__device__ __forceinline__ void atomicMaxFloat(float* addr, float val) {
    if (val == -INFINITY) return;
    if (val >= 0.0f) {
        atomicMax((int*)addr, __float_as_int(val));
    } else {
        atomicMin((unsigned int*)addr, __float_as_uint(val));
    }
}

// ---------------- kernel 1: init row/col max buffers to -inf ----------------
__global__ void init_kernel() {
    int i = blockIdx.x * blockDim.x + threadIdx.x;
    if (i < B_ * S_) {
        g_rowmax[i] = -INFINITY;
        g_colmax[i] = -INFINITY;
    }
}

// ---------------- kernel 2: normalize fp32 rows -> bf16 unit vectors ----------------
// grid: (B*S, 2), block: 192 threads (each thread handles one float4 = 4 elems; 192*4=768)
__global__ void normalize_kernel(const float* __restrict__ e1,
                                 const float* __restrict__ e2) {
    const int row = blockIdx.x;
    const float* src = (blockIdx.y ? e2 : e1) + (size_t)row * D_;
    __nv_bfloat16* dst = (blockIdx.y ? g_n2 : g_n1) + (size_t)row * D_;

    float4 v = *(const float4*)(src + threadIdx.x * 4);
    float ss = v.x * v.x + v.y * v.y + v.z * v.z + v.w * v.w;

    #pragma unroll
    for (int o = 16; o; o >>= 1) ss += __shfl_xor_sync(0xffffffffu, ss, o);

    __shared__ float ws[8];
    int lane = threadIdx.x & 31, w = threadIdx.x >> 5;
    if (lane == 0) ws[w] = ss;
    __syncthreads();
    if (threadIdx.x == 0) {
        float t = 0.f;
        #pragma unroll
        for (int i = 0; i < 6; i++) t += ws[i];
        ws[0] = 1.0f / fmaxf(sqrtf(t), EPS_);
    }
    __syncthreads();
    float s = ws[0];

    __nv_bfloat162 o0 = __floats2bfloat162_rn(v.x * s, v.y * s);
    __nv_bfloat162 o1 = __floats2bfloat162_rn(v.z * s, v.w * s);
    *(__nv_bfloat162*)(dst + threadIdx.x * 4)     = o0;
    *(__nv_bfloat162*)(dst + threadIdx.x * 4 + 2) = o1;
}

// ---------------- kernel 3: tiled bf16 GEMM (sim = n1 @ n2^T) + fused masked max ----------------
// CTA tile 128x128, 8 warps in 2(m) x 4(n), warp tile 64x32, mma m16n8k16.
// grid: (4 jt, 4 it, 32 b), block 256.
#define KC 64
#define SPAD 72   // 72 bf16 = 144 B row stride (16B aligned, conflict-free frag loads)

__global__ __launch_bounds__(256) void gemm_max_kernel(const int* __restrict__ mask1,
                                                       const int* __restrict__ mask2) {
    __shared__ __nv_bfloat16 As[128][SPAD];
    __shared__ __nv_bfloat16 Bs[128][SPAD];

    const int b  = blockIdx.z;
    const int i0 = blockIdx.y * 128;
    const int j0 = blockIdx.x * 128;

    const int lane = threadIdx.x & 31;
    const int g    = lane >> 2;      // 0..7
    const int tg   = lane & 3;       // 0..3
    const int warp = threadIdx.x >> 5;
    const int wm   = warp >> 2;      // 0..1
    const int wn   = warp & 3;       // 0..3

    float c[4][4][4];
    #pragma unroll
    for (int mf = 0; mf < 4; mf++)
        #pragma unroll
        for (int nf = 0; nf < 4; nf++)
            #pragma unroll
            for (int e = 0; e < 4; e++) c[mf][nf][e] = 0.0f;

    const __nv_bfloat16* Agbase = g_n1 + (size_t)(b * S_ + i0) * D_;
    const __nv_bfloat16* Bgbase = g_n2 + (size_t)(b * S_ + j0) * D_;

    for (int kk = 0; kk < D_; kk += KC) {
        // cooperative load: 128 x 64 bf16 per tile, uint4 granularity
        #pragma unroll
        for (int u = 0; u < 4; u++) {
            int idx = threadIdx.x + u * 256;      // 0..1023
            int r = idx >> 3;
            int cc = (idx & 7) * 8;
            *(uint4*)&As[r][cc] = *(const uint4*)(Agbase + (size_t)r * D_ + kk + cc);
            *(uint4*)&Bs[r][cc] = *(const uint4*)(Bgbase + (size_t)r * D_ + kk + cc);
        }
        __syncthreads();

        #pragma unroll
        for (int ks = 0; ks < KC / 16; ks++) {
            const int kb = ks * 16 + 2 * tg;
            unsigned a[4][4];
            unsigned bf[4][2];
            #pragma unroll
            for (int mf = 0; mf < 4; mf++) {
                const __nv_bfloat16* pr = &As[wm * 64 + mf * 16 + g][kb];
                a[mf][0] = *(const unsigned*)pr;
                a[mf][1] = *(const unsigned*)(pr + 8 * SPAD);
                a[mf][2] = *(const unsigned*)(pr + 8);
                a[mf][3] = *(const unsigned*)(pr + 8 * SPAD + 8);
            }
            #pragma unroll
            for (int nf = 0; nf < 4; nf++) {
                const __nv_bfloat16* pb = &Bs[wn * 32 + nf * 8 + g][kb];
                bf[nf][0] = *(const unsigned*)pb;
                bf[nf][1] = *(const unsigned*)(pb + 8);
            }
            #pragma unroll
            for (int mf = 0; mf < 4; mf++) {
                #pragma unroll
                for (int nf = 0; nf < 4; nf++) {
                    asm volatile(
                        "mma.sync.aligned.m16n8k16.row.col.f32.bf16.bf16.f32 "
                        "{%0,%1,%2,%3},{%4,%5,%6,%7},{%8,%9},{%0,%1,%2,%3};"
                        : "+f"(c[mf][nf][0]), "+f"(c[mf][nf][1]),
                          "+f"(c[mf][nf][2]), "+f"(c[mf][nf][3])
                        : "r"(a[mf][0]), "r"(a[mf][1]), "r"(a[mf][2]), "r"(a[mf][3]),
                          "r"(bf[nf][0]), "r"(bf[nf][1]));
                }
            }
        }
        __syncthreads();
    }

    // -------- fused masked max epilogue (register + shuffle reductions) --------
    const int baseRow = b * S_ + i0 + wm * 64;
    const int baseCol = b * S_ + j0 + wn * 32;

    int m1v[4][2], m2v[4][2];
    #pragma unroll
    for (int mf = 0; mf < 4; mf++) {
        m1v[mf][0] = mask1[baseRow + mf * 16 + g];
        m1v[mf][1] = mask1[baseRow + mf * 16 + g + 8];
    }
    #pragma unroll
    for (int nf = 0; nf < 4; nf++) {
        m2v[nf][0] = mask2[baseCol + nf * 8 + 2 * tg];
        m2v[nf][1] = mask2[baseCol + nf * 8 + 2 * tg + 1];
    }

    // row maxes: per (mf, y), reduce over this thread's 8 masked cols, then across tg lanes.
    #pragma unroll
    for (int mf = 0; mf < 4; mf++) {
        #pragma unroll
        for (int y = 0; y < 2; y++) {
            float r = -INFINITY;
            #pragma unroll
            for (int nf = 0; nf < 4; nf++) {
                if (m2v[nf][0]) r = fmaxf(r, c[mf][nf][y * 2 + 0]);
                if (m2v[nf][1]) r = fmaxf(r, c[mf][nf][y * 2 + 1]);
            }
            r = fmaxf(r, __shfl_xor_sync(0xffffffffu, r, 1));
            r = fmaxf(r, __shfl_xor_sync(0xffffffffu, r, 2));
            if (tg == 0)
                atomicMaxFloat(&g_rowmax[baseRow + mf * 16 + g + 8 * y], r);
        }
    }

    // col maxes: per (nf, x), reduce over this thread's 8 masked rows, then across g lanes.
    #pragma unroll
    for (int nf = 0; nf < 4; nf++) {
        #pragma unroll
        for (int x = 0; x < 2; x++) {
            float cm = -INFINITY;
            #pragma unroll
            for (int mf = 0; mf < 4; mf++) {
                if (m1v[mf][0]) cm = fmaxf(cm, c[mf][nf][0 * 2 + x]);
                if (m1v[mf][1]) cm = fmaxf(cm, c[mf][nf][1 * 2 + x]);
            }
            cm = fmaxf(cm, __shfl_xor_sync(0xffffffffu, cm, 4));
            cm = fmaxf(cm, __shfl_xor_sync(0xffffffffu, cm, 8));
            cm = fmaxf(cm, __shfl_xor_sync(0xffffffffu, cm, 16));
            if (g == 0)
                atomicMaxFloat(&g_colmax[baseCol + nf * 8 + 2 * tg + x], cm);
        }
    }
}

// ---------------- kernel 4: finalize per-batch score ----------------
__global__ void finalize_kernel(const int* __restrict__ mask1,
                                const int* __restrict__ mask2,
                                float* __restrict__ out) {
    const int b = blockIdx.x;
    const int t = threadIdx.x;   // 256 threads
    float sum = 0.0f;
    int cnt = 0;
    for (int i = t; i < S_; i += 256) {
        int a = mask1[b * S_ + i];
        cnt += a;
        if (a) sum += g_rowmax[b * S_ + i];
        int d = mask2[b * S_ + i];
        cnt += d;
        if (d) sum += g_colmax[b * S_ + i];
    }
    #pragma unroll
    for (int o = 16; o; o >>= 1) {
        sum += __shfl_xor_sync(0xffffffffu, sum, o);
        cnt += __shfl_xor_sync(0xffffffffu, cnt, o);
    }
    __shared__ float ssum[8];
    __shared__ int scnt[8];
    int lane = t & 31, w = t >> 5;
    if (lane == 0) { ssum[w] = sum; scnt[w] = cnt; }
    __syncthreads();
    if (t == 0) {
        float ts = 0.f; int tc = 0;
        #pragma unroll
        for (int i = 0; i < 8; i++) { ts += ssum[i]; tc += scnt[i]; }
        out[b] = ts / fmaxf((float)tc, 1.0f);
    }
}

// ---------------- launch ----------------
extern "C" void kernel_launch(void* const* d_in, const int* in_sizes, int n_in,
                              void* d_out, int out_size) {
    const float* emb1 = (const float*)d_in[0];
    const float* emb2 = (const float*)d_in[1];
    const int*   mask1 = (const int*)d_in[2];
    const int*   mask2 = (const int*)d_in[3];
    float* out = (float*)d_out;

    init_kernel<<<(B_ * S_ + 255) / 256, 256>>>();
    normalize_kernel<<<dim3(B_ * S_, 2), 192>>>(emb1, emb2);
    gemm_max_kernel<<<dim3(4, 4, B_), 256>>>(mask1, mask2);
    finalize_kernel<<<B_, 256>>>(mask1, mask2, out);
}

// round 3
// speedup vs baseline: 1.0932x; 1.0932x over previous
#include <cuda_runtime.h>
#include <cuda_bf16.h>
#include <cstdint>

#define B_   32
#define S_   512
#define D_   768
#define EPS_ 1e-8f

// ---------------- device scratch ----------------
__device__ __align__(16) __nv_bfloat16 g_n1[B_ * S_ * D_];
__device__ __align__(16) __nv_bfloat16 g_n2[B_ * S_ * D_];
__device__ unsigned g_rowmax[B_ * S_];   // order-preserving mapped fp32
__device__ unsigned g_colmax[B_ * S_];
__device__ int      g_arrive[B_];

// ---------------- helpers ----------------
__device__ __forceinline__ uint32_t smem_u32(const void* p) {
    uint32_t a;
    asm("{ .reg .u64 t; cvta.to.shared.u64 t, %1; cvt.u32.u64 %0, t; }" : "=r"(a) : "l"(p));
    return a;
}
__device__ __forceinline__ unsigned fmap(float x) {
    int i = __float_as_int(x);
    return (unsigned)(i ^ ((i >> 31) | 0x80000000));
}
__device__ __forceinline__ float fumap(unsigned u) {
    int i = (int)(u ^ ((u & 0x80000000u) ? 0x80000000u : 0xFFFFFFFFu));
    return __int_as_float(i);
}

#define CP_ASYNC16(dst, src) \
    asm volatile("cp.async.cg.shared.global [%0], [%1], 16;" :: "r"(dst), "l"(src))
#define CP_COMMIT() asm volatile("cp.async.commit_group;" ::: "memory")
#define CP_WAIT0()  asm volatile("cp.async.wait_group 0;" ::: "memory")
#define CP_WAIT1()  asm volatile("cp.async.wait_group 1;" ::: "memory")

#define LDMATRIX_X4(r0, r1, r2, r3, addr) \
    asm volatile("ldmatrix.sync.aligned.m8n8.x4.shared.b16 {%0,%1,%2,%3}, [%4];" \
                 : "=r"(r0), "=r"(r1), "=r"(r2), "=r"(r3) : "r"(addr))

// ---------------- kernel 1: normalize + all inits ----------------
__global__ void normalize_kernel(const float* __restrict__ e1,
                                 const float* __restrict__ e2) {
    const int row = blockIdx.x;
    const float* src = (blockIdx.y ? e2 : e1) + (size_t)row * D_;
    __nv_bfloat16* dst = (blockIdx.y ? g_n2 : g_n1) + (size_t)row * D_;

    if (blockIdx.y == 0 && threadIdx.x == 0) {
        g_rowmax[row] = 0u;                 // 0 < fmap(x) for every float x
        g_colmax[row] = 0u;
        if (row < B_) g_arrive[row] = 0;
    }

    float4 v = *(const float4*)(src + threadIdx.x * 4);
    float ss = v.x * v.x + v.y * v.y + v.z * v.z + v.w * v.w;
    #pragma unroll
    for (int o = 16; o; o >>= 1) ss += __shfl_xor_sync(0xffffffffu, ss, o);

    __shared__ float ws[8];
    int lane = threadIdx.x & 31, w = threadIdx.x >> 5;
    if (lane == 0) ws[w] = ss;
    __syncthreads();
    if (threadIdx.x == 0) {
        float t = 0.f;
        #pragma unroll
        for (int i = 0; i < 6; i++) t += ws[i];
        ws[0] = 1.0f / fmaxf(sqrtf(t), EPS_);
    }
    __syncthreads();
    float s = ws[0];

    *(__nv_bfloat162*)(dst + threadIdx.x * 4)     = __floats2bfloat162_rn(v.x * s, v.y * s);
    *(__nv_bfloat162*)(dst + threadIdx.x * 4 + 2) = __floats2bfloat162_rn(v.z * s, v.w * s);
}

// ---------------- kernel 2: pipelined HMMA GEMM + fused max epilogue + finalize ----
// CTA tile 128x128, 8 warps 2(m)x4(n), warp tile 64x32, mma m16n8k16 bf16.
// KC=64, 2-stage cp.async double buffer, ldmatrix.x4 fragment loads.
#define KC     64
#define SPAD   72                       // 144B row pitch
#define AT_BYTES (128 * SPAD * 2)       // 18432
#define STAGE_BYTES (2 * AT_BYTES)      // A + B
#define SMEM_TOTAL (2 * STAGE_BYTES)    // 73728

__device__ __forceinline__ void load_chunk(uint32_t sA, uint32_t sB,
                                           const __nv_bfloat16* gA,
                                           const __nv_bfloat16* gB,
                                           int kk, int tid) {
    #pragma unroll
    for (int i = 0; i < 4; i++) {
        int idx = tid + i * 256;                    // 0..1023
        int row = idx >> 3, seg = idx & 7;
        uint32_t off = row * (SPAD * 2) + seg * 16;
        CP_ASYNC16(sA + off, gA + (size_t)row * D_ + kk + seg * 8);
        CP_ASYNC16(sB + off, gB + (size_t)row * D_ + kk + seg * 8);
    }
}

__global__ __launch_bounds__(256, 2) void gemm_max_kernel(const int* __restrict__ mask1,
                                                          const int* __restrict__ mask2,
                                                          float* __restrict__ out) {
    extern __shared__ char smem[];
    const uint32_t sbase = smem_u32(smem);

    const int tid  = threadIdx.x;
    const int lane = tid & 31;
    const int g    = lane >> 2;
    const int tg   = lane & 3;
    const int warp = tid >> 5;
    const int wm   = warp >> 2;
    const int wn   = warp & 3;

    const int b  = blockIdx.z;
    const int i0 = blockIdx.y * 128;
    const int j0 = blockIdx.x * 128;

    float c[4][4][4];
    #pragma unroll
    for (int mf = 0; mf < 4; mf++)
        #pragma unroll
        for (int nf = 0; nf < 4; nf++)
            #pragma unroll
            for (int e = 0; e < 4; e++) c[mf][nf][e] = 0.0f;

    const __nv_bfloat16* gA = g_n1 + (size_t)(b * S_ + i0) * D_;
    const __nv_bfloat16* gB = g_n2 + (size_t)(b * S_ + j0) * D_;

    const uint32_t sA[2] = { sbase,                sbase + STAGE_BYTES };
    const uint32_t sB[2] = { sbase + AT_BYTES,     sbase + STAGE_BYTES + AT_BYTES };

    // per-lane ldmatrix address components (byte offsets within a tile)
    // A: lanes 0-15 -> rows 0..15 @ kb; lanes 16-31 -> rows 0..15 @ kb+8
    const uint32_t aoff = (uint32_t)((wm * 64 + (lane & 15)) * (SPAD * 2) + (lane >> 4) * 16);
    // B: row = wn*32 + (lane&7) + ((lane>>4)<<3) ; col = ((lane>>3)&1)*8
    const uint32_t boff = (uint32_t)((wn * 32 + (lane & 7) + ((lane >> 4) << 3)) * (SPAD * 2)
                                     + ((lane >> 3) & 1) * 16);

    load_chunk(sA[0], sB[0], gA, gB, 0,  tid); CP_COMMIT();
    load_chunk(sA[1], sB[1], gA, gB, KC, tid); CP_COMMIT();

    #pragma unroll 1
    for (int ch = 0; ch < 12; ch++) {
        const int buf = ch & 1;
        if (ch == 11) { CP_WAIT0(); } else { CP_WAIT1(); }
        __syncthreads();

        const uint32_t abase = sA[buf] + aoff;
        const uint32_t bbase = sB[buf] + boff;

        #pragma unroll
        for (int ks = 0; ks < KC / 16; ks++) {
            const uint32_t kb2 = ks * 32;          // kb*2 bytes
            unsigned a[4][4], bf[4][2];
            #pragma unroll
            for (int mf = 0; mf < 4; mf++)
                LDMATRIX_X4(a[mf][0], a[mf][1], a[mf][2], a[mf][3],
                            abase + mf * 16 * (SPAD * 2) + kb2);
            #pragma unroll
            for (int p = 0; p < 2; p++) {
                unsigned r0, r1, r2, r3;
                LDMATRIX_X4(r0, r1, r2, r3, bbase + p * 16 * (SPAD * 2) + kb2);
                bf[p * 2 + 0][0] = r0; bf[p * 2 + 0][1] = r1;
                bf[p * 2 + 1][0] = r2; bf[p * 2 + 1][1] = r3;
            }
            #pragma unroll
            for (int mf = 0; mf < 4; mf++)
                #pragma unroll
                for (int nf = 0; nf < 4; nf++)
                    asm volatile(
                        "mma.sync.aligned.m16n8k16.row.col.f32.bf16.bf16.f32 "
                        "{%0,%1,%2,%3},{%4,%5,%6,%7},{%8,%9},{%0,%1,%2,%3};"
                        : "+f"(c[mf][nf][0]), "+f"(c[mf][nf][1]),
                          "+f"(c[mf][nf][2]), "+f"(c[mf][nf][3])
                        : "r"(a[mf][0]), "r"(a[mf][1]), "r"(a[mf][2]), "r"(a[mf][3]),
                          "r"(bf[nf][0]), "r"(bf[nf][1]));
        }

        __syncthreads();
        if (ch + 2 < 12) {
            load_chunk(sA[buf], sB[buf], gA, gB, (ch + 2) * KC, tid);
            CP_COMMIT();
        }
    }

    // -------- fused masked max epilogue --------
    const int baseRow = b * S_ + i0 + wm * 64;
    const int baseCol = b * S_ + j0 + wn * 32;

    int m1v[4][2], m2v[4][2];
    #pragma unroll
    for (int mf = 0; mf < 4; mf++) {
        m1v[mf][0] = mask1[baseRow + mf * 16 + g];
        m1v[mf][1] = mask1[baseRow + mf * 16 + g + 8];
    }
    #pragma unroll
    for (int nf = 0; nf < 4; nf++) {
        m2v[nf][0] = mask2[baseCol + nf * 8 + 2 * tg];
        m2v[nf][1] = mask2[baseCol + nf * 8 + 2 * tg + 1];
    }

    #pragma unroll
    for (int mf = 0; mf < 4; mf++)
        #pragma unroll
        for (int y = 0; y < 2; y++) {
            float r = -INFINITY;
            #pragma unroll
            for (int nf = 0; nf < 4; nf++) {
                if (m2v[nf][0]) r = fmaxf(r, c[mf][nf][y * 2 + 0]);
                if (m2v[nf][1]) r = fmaxf(r, c[mf][nf][y * 2 + 1]);
            }
            r = fmaxf(r, __shfl_xor_sync(0xffffffffu, r, 1));
            r = fmaxf(r, __shfl_xor_sync(0xffffffffu, r, 2));
            if (tg == 0)
                atomicMax(&g_rowmax[baseRow + mf * 16 + g + 8 * y], fmap(r));
        }

    #pragma unroll
    for (int nf = 0; nf < 4; nf++)
        #pragma unroll
        for (int x = 0; x < 2; x++) {
            float cm = -INFINITY;
            #pragma unroll
            for (int mf = 0; mf < 4; mf++) {
                if (m1v[mf][0]) cm = fmaxf(cm, c[mf][nf][0 * 2 + x]);
                if (m1v[mf][1]) cm = fmaxf(cm, c[mf][nf][1 * 2 + x]);
            }
            cm = fmaxf(cm, __shfl_xor_sync(0xffffffffu, cm, 4));
            cm = fmaxf(cm, __shfl_xor_sync(0xffffffffu, cm, 8));
            cm = fmaxf(cm, __shfl_xor_sync(0xffffffffu, cm, 16));
            if (g == 0)
                atomicMax(&g_colmax[baseCol + nf * 8 + 2 * tg + x], fmap(cm));
        }

    // -------- fused finalize: 16th-arriving CTA per batch computes score --------
    __shared__ float fsum[8];
    __shared__ int   fcnt[8];
    __shared__ int   s_old;

    __threadfence();
    if (tid == 0) s_old = atomicAdd(&g_arrive[b], 1);
    __syncthreads();
    if (s_old == 15) {
        __threadfence();
        float sum = 0.0f;
        int cnt = 0;
        for (int j = tid; j < S_; j += 256) {
            int a1 = mask1[b * S_ + j];
            int a2 = mask2[b * S_ + j];
            cnt += a1 + a2;
            if (a1) sum += fumap(__ldcg(&g_rowmax[b * S_ + j]));
            if (a2) sum += fumap(__ldcg(&g_colmax[b * S_ + j]));
        }
        #pragma unroll
        for (int o = 16; o; o >>= 1) {
            sum += __shfl_xor_sync(0xffffffffu, sum, o);
            cnt += __shfl_xor_sync(0xffffffffu, cnt, o);
        }
        if (lane == 0) { fsum[warp] = sum; fcnt[warp] = cnt; }
        __syncthreads();
        if (tid == 0) {
            float ts = 0.f; int tc = 0;
            #pragma unroll
            for (int i = 0; i < 8; i++) { ts += fsum[i]; tc += fcnt[i]; }
            out[b] = ts / fmaxf((float)tc, 1.0f);
            g_arrive[b] = 0;   // reset for graph replay
        }
    }
}

// ---------------- launch ----------------
extern "C" void kernel_launch(void* const* d_in, const int* in_sizes, int n_in,
                              void* d_out, int out_size) {
    const float* emb1 = (const float*)d_in[0];
    const float* emb2 = (const float*)d_in[1];
    const int*   mask1 = (const int*)d_in[2];
    const int*   mask2 = (const int*)d_in[3];
    float* out = (float*)d_out;

    cudaFuncSetAttribute(gemm_max_kernel,
                         cudaFuncAttributeMaxDynamicSharedMemorySize, SMEM_TOTAL);

    normalize_kernel<<<dim3(B_ * S_, 2), 192>>>(emb1, emb2);
    gemm_max_kernel<<<dim3(4, 4, B_), 256, SMEM_TOTAL>>>(mask1, mask2, out);
}

// round 4
// speedup vs baseline: 1.1489x; 1.0510x over previous
#include <cuda_runtime.h>
#include <cuda_bf16.h>
#include <cstdint>

#define B_   32
#define S_   512
#define D_   768
#define EPS_ 1e-8f

// ---------------- device scratch ----------------
__device__ __align__(16) __nv_bfloat16 g_n1[B_ * S_ * D_];
__device__ __align__(16) __nv_bfloat16 g_n2[B_ * S_ * D_];
__device__ unsigned g_rowmax[B_ * S_];   // order-preserving mapped fp32
__device__ unsigned g_colmax[B_ * S_];
__device__ int      g_arrive[B_];

// ---------------- helpers ----------------
__device__ __forceinline__ uint32_t smem_u32(const void* p) {
    uint32_t a;
    asm("{ .reg .u64 t; cvta.to.shared.u64 t, %1; cvt.u32.u64 %0, t; }" : "=r"(a) : "l"(p));
    return a;
}
__device__ __forceinline__ unsigned fmap(float x) {
    int i = __float_as_int(x);
    return (unsigned)(i ^ ((i >> 31) | 0x80000000));
}
__device__ __forceinline__ float fumap(unsigned u) {
    int i = (int)(u ^ ((u & 0x80000000u) ? 0x80000000u : 0xFFFFFFFFu));
    return __int_as_float(i);
}

#define CP_ASYNC16(dst, src) \
    asm volatile("cp.async.cg.shared.global [%0], [%1], 16;" :: "r"(dst), "l"(src))
#define CP_COMMIT() asm volatile("cp.async.commit_group;" ::: "memory")
#define CP_WAIT2()  asm volatile("cp.async.wait_group 2;" ::: "memory")
#define CP_WAIT0()  asm volatile("cp.async.wait_group 0;" ::: "memory")

#define LDMATRIX_X4(r0, r1, r2, r3, addr) \
    asm volatile("ldmatrix.sync.aligned.m8n8.x4.shared.b16 {%0,%1,%2,%3}, [%4];" \
                 : "=r"(r0), "=r"(r1), "=r"(r2), "=r"(r3) : "r"(addr))

// ---------------- kernel 1: normalize + all inits ----------------
__global__ void normalize_kernel(const float* __restrict__ e1,
                                 const float* __restrict__ e2) {
    const int row = blockIdx.x;
    const float* src = (blockIdx.y ? e2 : e1) + (size_t)row * D_;
    __nv_bfloat16* dst = (blockIdx.y ? g_n2 : g_n1) + (size_t)row * D_;

    if (blockIdx.y == 0 && threadIdx.x == 0) {
        g_rowmax[row] = 0u;                 // 0 < fmap(x) for every float x
        g_colmax[row] = 0u;
        if (row < B_) g_arrive[row] = 0;
    }

    // evict-first read of the fp32 inputs: keep L2 for the bf16 scratch
    const float4* p = (const float4*)(src + threadIdx.x * 4);
    float4 v = __ldcs(p);
    float ss = v.x * v.x + v.y * v.y + v.z * v.z + v.w * v.w;
    #pragma unroll
    for (int o = 16; o; o >>= 1) ss += __shfl_xor_sync(0xffffffffu, ss, o);

    __shared__ float ws[8];
    int lane = threadIdx.x & 31, w = threadIdx.x >> 5;
    if (lane == 0) ws[w] = ss;
    __syncthreads();
    if (threadIdx.x == 0) {
        float t = 0.f;
        #pragma unroll
        for (int i = 0; i < 6; i++) t += ws[i];
        ws[0] = 1.0f / fmaxf(sqrtf(t), EPS_);
    }
    __syncthreads();
    float s = ws[0];

    *(__nv_bfloat162*)(dst + threadIdx.x * 4)     = __floats2bfloat162_rn(v.x * s, v.y * s);
    *(__nv_bfloat162*)(dst + threadIdx.x * 4 + 2) = __floats2bfloat162_rn(v.z * s, v.w * s);
}

// ---------------- kernel 2: pipelined HMMA GEMM + fused max epilogue + finalize ----
// CTA tile 128x128, 8 warps 2(m)x4(n), warp tile 64x32, mma m16n8k16 bf16.
// KC=64, 3-stage cp.async ring (refill before wait), ldmatrix frag double-buffer.
#define KC     64
#define NCH    (D_ / KC)                // 12
#define SPAD   72                       // 144B row pitch
#define AT_BYTES (128 * SPAD * 2)       // 18432
#define STAGE_BYTES (2 * AT_BYTES)      // A + B
#define SMEM_TOTAL (3 * STAGE_BYTES)    // 110592

__device__ __forceinline__ void load_chunk(uint32_t sA, uint32_t sB,
                                           const __nv_bfloat16* gA,
                                           const __nv_bfloat16* gB,
                                           int kk, int tid) {
    #pragma unroll
    for (int i = 0; i < 4; i++) {
        int idx = tid + i * 256;                    // 0..1023
        int row = idx >> 3, seg = idx & 7;
        uint32_t off = row * (SPAD * 2) + seg * 16;
        CP_ASYNC16(sA + off, gA + (size_t)row * D_ + kk + seg * 8);
        CP_ASYNC16(sB + off, gB + (size_t)row * D_ + kk + seg * 8);
    }
}

__global__ __launch_bounds__(256, 2) void gemm_max_kernel(const int* __restrict__ mask1,
                                                          const int* __restrict__ mask2,
                                                          float* __restrict__ out) {
    extern __shared__ char smem[];
    const uint32_t sbase = smem_u32(smem);

    const int tid  = threadIdx.x;
    const int lane = tid & 31;
    const int g    = lane >> 2;
    const int tg   = lane & 3;
    const int warp = tid >> 5;
    const int wm   = warp >> 2;
    const int wn   = warp & 3;

    const int b  = blockIdx.z;
    const int i0 = blockIdx.y * 128;
    const int j0 = blockIdx.x * 128;

    float c[4][4][4];
    #pragma unroll
    for (int mf = 0; mf < 4; mf++)
        #pragma unroll
        for (int nf = 0; nf < 4; nf++)
            #pragma unroll
            for (int e = 0; e < 4; e++) c[mf][nf][e] = 0.0f;

    const __nv_bfloat16* gA = g_n1 + (size_t)(b * S_ + i0) * D_;
    const __nv_bfloat16* gB = g_n2 + (size_t)(b * S_ + j0) * D_;

    uint32_t sA[3], sB[3];
    #pragma unroll
    for (int s = 0; s < 3; s++) {
        sA[s] = sbase + s * STAGE_BYTES;
        sB[s] = sbase + s * STAGE_BYTES + AT_BYTES;
    }

    // per-lane ldmatrix base offsets (bytes within a tile)
    const uint32_t aoff = (uint32_t)((wm * 64 + (lane & 15)) * (SPAD * 2) + (lane >> 4) * 16);
    const uint32_t boff = (uint32_t)((wn * 32 + (lane & 7) + ((lane >> 4) << 3)) * (SPAD * 2)
                                     + ((lane >> 3) & 1) * 16);

    // prologue: chunks 0,1 in flight
    load_chunk(sA[0], sB[0], gA, gB, 0,  tid); CP_COMMIT();
    load_chunk(sA[1], sB[1], gA, gB, KC, tid); CP_COMMIT();

    unsigned af[2][4][4], bfr[2][4][2];

    #pragma unroll 1
    for (int ch = 0; ch < NCH; ch++) {
        const int buf = ch % 3;

        __syncthreads();                       // all warps done with buf (ch+2)%3 == (ch-1)%3
        if (ch + 2 < NCH) {
            load_chunk(sA[(ch + 2) % 3], sB[(ch + 2) % 3], gA, gB, (ch + 2) * KC, tid);
            CP_COMMIT();
        }
        if (ch + 2 < NCH) { CP_WAIT2(); } else { CP_WAIT0(); }
        __syncthreads();                       // chunk ch visible to all warps

        const uint32_t abase = sA[buf] + aoff;
        const uint32_t bbase = sB[buf] + boff;

        // preload ks=0 fragments
        #pragma unroll
        for (int mf = 0; mf < 4; mf++)
            LDMATRIX_X4(af[0][mf][0], af[0][mf][1], af[0][mf][2], af[0][mf][3],
                        abase + mf * 16 * (SPAD * 2));
        #pragma unroll
        for (int p = 0; p < 2; p++) {
            unsigned r0, r1, r2, r3;
            LDMATRIX_X4(r0, r1, r2, r3, bbase + p * 16 * (SPAD * 2));
            bfr[0][p * 2 + 0][0] = r0; bfr[0][p * 2 + 0][1] = r1;
            bfr[0][p * 2 + 1][0] = r2; bfr[0][p * 2 + 1][1] = r3;
        }

        #pragma unroll
        for (int ks = 0; ks < KC / 16; ks++) {
            const int cur = ks & 1, nxt = cur ^ 1;
            if (ks + 1 < KC / 16) {
                const uint32_t kb2 = (ks + 1) * 32;
                #pragma unroll
                for (int mf = 0; mf < 4; mf++)
                    LDMATRIX_X4(af[nxt][mf][0], af[nxt][mf][1], af[nxt][mf][2], af[nxt][mf][3],
                                abase + mf * 16 * (SPAD * 2) + kb2);
                #pragma unroll
                for (int p = 0; p < 2; p++) {
                    unsigned r0, r1, r2, r3;
                    LDMATRIX_X4(r0, r1, r2, r3, bbase + p * 16 * (SPAD * 2) + kb2);
                    bfr[nxt][p * 2 + 0][0] = r0; bfr[nxt][p * 2 + 0][1] = r1;
                    bfr[nxt][p * 2 + 1][0] = r2; bfr[nxt][p * 2 + 1][1] = r3;
                }
            }
            #pragma unroll
            for (int mf = 0; mf < 4; mf++)
                #pragma unroll
                for (int nf = 0; nf < 4; nf++)
                    asm volatile(
                        "mma.sync.aligned.m16n8k16.row.col.f32.bf16.bf16.f32 "
                        "{%0,%1,%2,%3},{%4,%5,%6,%7},{%8,%9},{%0,%1,%2,%3};"
                        : "+f"(c[mf][nf][0]), "+f"(c[mf][nf][1]),
                          "+f"(c[mf][nf][2]), "+f"(c[mf][nf][3])
                        : "r"(af[cur][mf][0]), "r"(af[cur][mf][1]),
                          "r"(af[cur][mf][2]), "r"(af[cur][mf][3]),
                          "r"(bfr[cur][nf][0]), "r"(bfr[cur][nf][1]));
        }
    }

    // -------- fused masked max epilogue --------
    const int baseRow = b * S_ + i0 + wm * 64;
    const int baseCol = b * S_ + j0 + wn * 32;

    int m1v[4][2], m2v[4][2];
    #pragma unroll
    for (int mf = 0; mf < 4; mf++) {
        m1v[mf][0] = mask1[baseRow + mf * 16 + g];
        m1v[mf][1] = mask1[baseRow + mf * 16 + g + 8];
    }
    #pragma unroll
    for (int nf = 0; nf < 4; nf++) {
        m2v[nf][0] = mask2[baseCol + nf * 8 + 2 * tg];
        m2v[nf][1] = mask2[baseCol + nf * 8 + 2 * tg + 1];
    }

    #pragma unroll
    for (int mf = 0; mf < 4; mf++)
        #pragma unroll
        for (int y = 0; y < 2; y++) {
            float r = -INFINITY;
            #pragma unroll
            for (int nf = 0; nf < 4; nf++) {
                if (m2v[nf][0]) r = fmaxf(r, c[mf][nf][y * 2 + 0]);
                if (m2v[nf][1]) r = fmaxf(r, c[mf][nf][y * 2 + 1]);
            }
            r = fmaxf(r, __shfl_xor_sync(0xffffffffu, r, 1));
            r = fmaxf(r, __shfl_xor_sync(0xffffffffu, r, 2));
            if (tg == 0)
                atomicMax(&g_rowmax[baseRow + mf * 16 + g + 8 * y], fmap(r));
        }

    #pragma unroll
    for (int nf = 0; nf < 4; nf++)
        #pragma unroll
        for (int x = 0; x < 2; x++) {
            float cm = -INFINITY;
            #pragma unroll
            for (int mf = 0; mf < 4; mf++) {
                if (m1v[mf][0]) cm = fmaxf(cm, c[mf][nf][0 * 2 + x]);
                if (m1v[mf][1]) cm = fmaxf(cm, c[mf][nf][1 * 2 + x]);
            }
            cm = fmaxf(cm, __shfl_xor_sync(0xffffffffu, cm, 4));
            cm = fmaxf(cm, __shfl_xor_sync(0xffffffffu, cm, 8));
            cm = fmaxf(cm, __shfl_xor_sync(0xffffffffu, cm, 16));
            if (g == 0)
                atomicMax(&g_colmax[baseCol + nf * 8 + 2 * tg + x], fmap(cm));
        }

    // -------- fused finalize: 16th-arriving CTA per batch computes score --------
    __shared__ float fsum[8];
    __shared__ int   fcnt[8];
    __shared__ int   s_old;

    __threadfence();
    if (tid == 0) s_old = atomicAdd(&g_arrive[b], 1);
    __syncthreads();
    if (s_old == 15) {
        __threadfence();
        float sum = 0.0f;
        int cnt = 0;
        for (int j = tid; j < S_; j += 256) {
            int a1 = mask1[b * S_ + j];
            int a2 = mask2[b * S_ + j];
            cnt += a1 + a2;
            if (a1) sum += fumap(__ldcg(&g_rowmax[b * S_ + j]));
            if (a2) sum += fumap(__ldcg(&g_colmax[b * S_ + j]));
        }
        #pragma unroll
        for (int o = 16; o; o >>= 1) {
            sum += __shfl_xor_sync(0xffffffffu, sum, o);
            cnt += __shfl_xor_sync(0xffffffffu, cnt, o);
        }
        if (lane == 0) { fsum[warp] = sum; fcnt[warp] = cnt; }
        __syncthreads();
        if (tid == 0) {
            float ts = 0.f; int tc = 0;
            #pragma unroll
            for (int i = 0; i < 8; i++) { ts += fsum[i]; tc += fcnt[i]; }
            out[b] = ts / fmaxf((float)tc, 1.0f);
            g_arrive[b] = 0;   // reset for graph replay
        }
    }
}

// ---------------- launch ----------------
extern "C" void kernel_launch(void* const* d_in, const int* in_sizes, int n_in,
                              void* d_out, int out_size) {
    const float* emb1 = (const float*)d_in[0];
    const float* emb2 = (const float*)d_in[1];
    const int*   mask1 = (const int*)d_in[2];
    const int*   mask2 = (const int*)d_in[3];
    float* out = (float*)d_out;

    cudaFuncSetAttribute(gemm_max_kernel,
                         cudaFuncAttributeMaxDynamicSharedMemorySize, SMEM_TOTAL);

    normalize_kernel<<<dim3(B_ * S_, 2), 192>>>(emb1, emb2);
    gemm_max_kernel<<<dim3(4, 4, B_), 256, SMEM_TOTAL>>>(mask1, mask2, out);
}

// round 5
// speedup vs baseline: 1.1794x; 1.0266x over previous
#include <cuda_runtime.h>
#include <cuda_bf16.h>
#include <cstdint>

#define B_   32
#define S_   512
#define D_   768
#define EPS_ 1e-8f

// ---------------- device scratch ----------------
__device__ __align__(16) __nv_bfloat16 g_n1[B_ * S_ * D_];
__device__ __align__(16) __nv_bfloat16 g_n2[B_ * S_ * D_];
__device__ unsigned g_rowmax[B_ * S_];   // order-preserving mapped fp32
__device__ unsigned g_colmax[B_ * S_];
__device__ int      g_arrive[B_];

// ---------------- helpers ----------------
__device__ __forceinline__ uint32_t smem_u32(const void* p) {
    uint32_t a;
    asm("{ .reg .u64 t; cvta.to.shared.u64 t, %1; cvt.u32.u64 %0, t; }" : "=r"(a) : "l"(p));
    return a;
}
__device__ __forceinline__ unsigned fmap(float x) {
    int i = __float_as_int(x);
    return (unsigned)(i ^ ((i >> 31) | 0x80000000));
}
__device__ __forceinline__ float fumap(unsigned u) {
    int i = (int)(u ^ ((u & 0x80000000u) ? 0x80000000u : 0xFFFFFFFFu));
    return __int_as_float(i);
}

#define CP_ASYNC16(dst, src) \
    asm volatile("cp.async.cg.shared.global [%0], [%1], 16;" :: "r"(dst), "l"(src))
#define CP_COMMIT() asm volatile("cp.async.commit_group;" ::: "memory")
#define CP_WAIT1()  asm volatile("cp.async.wait_group 1;" ::: "memory")
#define CP_WAIT0()  asm volatile("cp.async.wait_group 0;" ::: "memory")

#define LDMATRIX_X4(r0, r1, r2, r3, addr) \
    asm volatile("ldmatrix.sync.aligned.m8n8.x4.shared.b16 {%0,%1,%2,%3}, [%4];" \
                 : "=r"(r0), "=r"(r1), "=r"(r2), "=r"(r3) : "r"(addr))

// ---------------- kernel 1: normalize (warp per row) + all inits ----------------
// block 256 = 8 warps = 8 rows; grid (2048, 2). No smem, no __syncthreads.
__global__ __launch_bounds__(256) void normalize_kernel(const float* __restrict__ e1,
                                                        const float* __restrict__ e2) {
    const int lane = threadIdx.x & 31;
    const int wrp  = threadIdx.x >> 5;
    const int row  = blockIdx.x * 8 + wrp;

    if (blockIdx.y == 0 && blockIdx.x < 64) {
        int t = blockIdx.x * 256 + threadIdx.x;   // covers exactly 16384
        g_rowmax[t] = 0u;                          // 0 < fmap(x) for all x
        g_colmax[t] = 0u;
        if (t < B_) g_arrive[t] = 0;
    }

    const float* src = (blockIdx.y ? e2 : e1) + (size_t)row * D_;
    __nv_bfloat16* dst = (blockIdx.y ? g_n2 : g_n1) + (size_t)row * D_;

    float4 v[6];
    float ss = 0.0f;
    #pragma unroll
    for (int k = 0; k < 6; k++) {
        v[k] = __ldcs((const float4*)(src + lane * 4 + k * 128));
        ss += v[k].x * v[k].x + v[k].y * v[k].y + v[k].z * v[k].z + v[k].w * v[k].w;
    }
    #pragma unroll
    for (int o = 16; o; o >>= 1) ss += __shfl_xor_sync(0xffffffffu, ss, o);

    const float s = 1.0f / fmaxf(sqrtf(ss), EPS_);

    #pragma unroll
    for (int k = 0; k < 6; k++) {
        *(__nv_bfloat162*)(dst + lane * 4 + k * 128)     = __floats2bfloat162_rn(v[k].x * s, v[k].y * s);
        *(__nv_bfloat162*)(dst + lane * 4 + k * 128 + 2) = __floats2bfloat162_rn(v[k].z * s, v[k].w * s);
    }
}

// ---------------- kernel 2: pipelined HMMA GEMM + fused max epilogue + finalize ----
// CTA tile 128x128, 8 warps 2(m)x4(n), warp tile 64x32, mma m16n8k16 bf16.
// KC=64, 3-stage cp.async ring, ONE __syncthreads per chunk, loads interleaved
// between ks groups, ldmatrix fragment double-buffer.
#define KC     64
#define NCH    (D_ / KC)                // 12
#define SPAD   72                       // 144B row pitch
#define AT_BYTES (128 * SPAD * 2)       // 18432
#define STAGE_BYTES (2 * AT_BYTES)      // A + B
#define SMEM_TOTAL (3 * STAGE_BYTES)    // 110592

__device__ __forceinline__ void load_quarter(uint32_t sA, uint32_t sB,
                                             const __nv_bfloat16* gA,
                                             const __nv_bfloat16* gB,
                                             int kk, int tid, int q) {
    int idx = tid + q * 256;                       // 0..1023
    int row = idx >> 3, seg = idx & 7;
    uint32_t off = row * (SPAD * 2) + seg * 16;
    CP_ASYNC16(sA + off, gA + (size_t)row * D_ + kk + seg * 8);
    CP_ASYNC16(sB + off, gB + (size_t)row * D_ + kk + seg * 8);
}

__global__ __launch_bounds__(256, 2) void gemm_max_kernel(const int* __restrict__ mask1,
                                                          const int* __restrict__ mask2,
                                                          float* __restrict__ out) {
    extern __shared__ char smem[];
    const uint32_t sbase = smem_u32(smem);

    const int tid  = threadIdx.x;
    const int lane = tid & 31;
    const int g    = lane >> 2;
    const int tg   = lane & 3;
    const int warp = tid >> 5;
    const int wm   = warp >> 2;
    const int wn   = warp & 3;

    const int b  = blockIdx.z;
    const int i0 = blockIdx.y * 128;
    const int j0 = blockIdx.x * 128;

    float c[4][4][4];
    #pragma unroll
    for (int mf = 0; mf < 4; mf++)
        #pragma unroll
        for (int nf = 0; nf < 4; nf++)
            #pragma unroll
            for (int e = 0; e < 4; e++) c[mf][nf][e] = 0.0f;

    const __nv_bfloat16* gA = g_n1 + (size_t)(b * S_ + i0) * D_;
    const __nv_bfloat16* gB = g_n2 + (size_t)(b * S_ + j0) * D_;

    uint32_t sA[3], sB[3];
    #pragma unroll
    for (int s = 0; s < 3; s++) {
        sA[s] = sbase + s * STAGE_BYTES;
        sB[s] = sbase + s * STAGE_BYTES + AT_BYTES;
    }

    const uint32_t aoff = (uint32_t)((wm * 64 + (lane & 15)) * (SPAD * 2) + (lane >> 4) * 16);
    const uint32_t boff = (uint32_t)((wn * 32 + (lane & 7) + ((lane >> 4) << 3)) * (SPAD * 2)
                                     + ((lane >> 3) & 1) * 16);

    // prologue: chunks 0,1 in flight
    #pragma unroll
    for (int q = 0; q < 4; q++) load_quarter(sA[0], sB[0], gA, gB, 0,  tid, q);
    CP_COMMIT();
    #pragma unroll
    for (int q = 0; q < 4; q++) load_quarter(sA[1], sB[1], gA, gB, KC, tid, q);
    CP_COMMIT();

    unsigned af[2][4][4], bfr[2][4][2];

    #pragma unroll 1
    for (int ch = 0; ch < NCH; ch++) {
        const int buf = ch % 3;

        if (ch == NCH - 1) { CP_WAIT0(); } else { CP_WAIT1(); }
        __syncthreads();          // publishes chunk ch; also: all warps done with (ch+2)%3

        const uint32_t abase = sA[buf] + aoff;
        const uint32_t bbase = sB[buf] + boff;
        const bool doLoad = (ch + 2 < NCH);
        const int ld = (ch + 2) % 3;
        const int kkn = (ch + 2) * KC;

        // preload ks=0 fragments
        #pragma unroll
        for (int mf = 0; mf < 4; mf++)
            LDMATRIX_X4(af[0][mf][0], af[0][mf][1], af[0][mf][2], af[0][mf][3],
                        abase + mf * 16 * (SPAD * 2));
        #pragma unroll
        for (int p = 0; p < 2; p++) {
            unsigned r0, r1, r2, r3;
            LDMATRIX_X4(r0, r1, r2, r3, bbase + p * 16 * (SPAD * 2));
            bfr[0][p * 2 + 0][0] = r0; bfr[0][p * 2 + 0][1] = r1;
            bfr[0][p * 2 + 1][0] = r2; bfr[0][p * 2 + 1][1] = r3;
        }

        #pragma unroll
        for (int ks = 0; ks < KC / 16; ks++) {
            const int cur = ks & 1, nxt = cur ^ 1;
            if (ks + 1 < KC / 16) {
                const uint32_t kb2 = (ks + 1) * 32;
                #pragma unroll
                for (int mf = 0; mf < 4; mf++)
                    LDMATRIX_X4(af[nxt][mf][0], af[nxt][mf][1], af[nxt][mf][2], af[nxt][mf][3],
                                abase + mf * 16 * (SPAD * 2) + kb2);
                #pragma unroll
                for (int p = 0; p < 2; p++) {
                    unsigned r0, r1, r2, r3;
                    LDMATRIX_X4(r0, r1, r2, r3, bbase + p * 16 * (SPAD * 2) + kb2);
                    bfr[nxt][p * 2 + 0][0] = r0; bfr[nxt][p * 2 + 0][1] = r1;
                    bfr[nxt][p * 2 + 1][0] = r2; bfr[nxt][p * 2 + 1][1] = r3;
                }
            }
            // interleave one quarter of next chunk's cp.async between ks groups
            if (doLoad) load_quarter(sA[ld], sB[ld], gA, gB, kkn, tid, ks);

            #pragma unroll
            for (int mf = 0; mf < 4; mf++)
                #pragma unroll
                for (int nf = 0; nf < 4; nf++)
                    asm volatile(
                        "mma.sync.aligned.m16n8k16.row.col.f32.bf16.bf16.f32 "
                        "{%0,%1,%2,%3},{%4,%5,%6,%7},{%8,%9},{%0,%1,%2,%3};"
                        : "+f"(c[mf][nf][0]), "+f"(c[mf][nf][1]),
                          "+f"(c[mf][nf][2]), "+f"(c[mf][nf][3])
                        : "r"(af[cur][mf][0]), "r"(af[cur][mf][1]),
                          "r"(af[cur][mf][2]), "r"(af[cur][mf][3]),
                          "r"(bfr[cur][nf][0]), "r"(bfr[cur][nf][1]));
        }
        if (doLoad) CP_COMMIT();
    }

    // -------- fused masked max epilogue --------
    const int baseRow = b * S_ + i0 + wm * 64;
    const int baseCol = b * S_ + j0 + wn * 32;

    int m1v[4][2], m2v[4][2];
    #pragma unroll
    for (int mf = 0; mf < 4; mf++) {
        m1v[mf][0] = mask1[baseRow + mf * 16 + g];
        m1v[mf][1] = mask1[baseRow + mf * 16 + g + 8];
    }
    #pragma unroll
    for (int nf = 0; nf < 4; nf++) {
        m2v[nf][0] = mask2[baseCol + nf * 8 + 2 * tg];
        m2v[nf][1] = mask2[baseCol + nf * 8 + 2 * tg + 1];
    }

    #pragma unroll
    for (int mf = 0; mf < 4; mf++)
        #pragma unroll
        for (int y = 0; y < 2; y++) {
            float r = -INFINITY;
            #pragma unroll
            for (int nf = 0; nf < 4; nf++) {
                if (m2v[nf][0]) r = fmaxf(r, c[mf][nf][y * 2 + 0]);
                if (m2v[nf][1]) r = fmaxf(r, c[mf][nf][y * 2 + 1]);
            }
            r = fmaxf(r, __shfl_xor_sync(0xffffffffu, r, 1));
            r = fmaxf(r, __shfl_xor_sync(0xffffffffu, r, 2));
            if (tg == 0)
                atomicMax(&g_rowmax[baseRow + mf * 16 + g + 8 * y], fmap(r));
        }

    #pragma unroll
    for (int nf = 0; nf < 4; nf++)
        #pragma unroll
        for (int x = 0; x < 2; x++) {
            float cm = -INFINITY;
            #pragma unroll
            for (int mf = 0; mf < 4; mf++) {
                if (m1v[mf][0]) cm = fmaxf(cm, c[mf][nf][0 * 2 + x]);
                if (m1v[mf][1]) cm = fmaxf(cm, c[mf][nf][1 * 2 + x]);
            }
            cm = fmaxf(cm, __shfl_xor_sync(0xffffffffu, cm, 4));
            cm = fmaxf(cm, __shfl_xor_sync(0xffffffffu, cm, 8));
            cm = fmaxf(cm, __shfl_xor_sync(0xffffffffu, cm, 16));
            if (g == 0)
                atomicMax(&g_colmax[baseCol + nf * 8 + 2 * tg + x], fmap(cm));
        }

    // -------- fused finalize: 16th-arriving CTA per batch computes score --------
    __shared__ float fsum[8];
    __shared__ int   fcnt[8];
    __shared__ int   s_old;

    __threadfence();
    if (tid == 0) s_old = atomicAdd(&g_arrive[b], 1);
    __syncthreads();
    if (s_old == 15) {
        __threadfence();
        float sum = 0.0f;
        int cnt = 0;
        for (int j = tid; j < S_; j += 256) {
            int a1 = mask1[b * S_ + j];
            int a2 = mask2[b * S_ + j];
            cnt += a1 + a2;
            if (a1) sum += fumap(__ldcg(&g_rowmax[b * S_ + j]));
            if (a2) sum += fumap(__ldcg(&g_colmax[b * S_ + j]));
        }
        #pragma unroll
        for (int o = 16; o; o >>= 1) {
            sum += __shfl_xor_sync(0xffffffffu, sum, o);
            cnt += __shfl_xor_sync(0xffffffffu, cnt, o);
        }
        if (lane == 0) { fsum[warp] = sum; fcnt[warp] = cnt; }
        __syncthreads();
        if (tid == 0) {
            float ts = 0.f; int tc = 0;
            #pragma unroll
            for (int i = 0; i < 8; i++) { ts += fsum[i]; tc += fcnt[i]; }
            out[b] = ts / fmaxf((float)tc, 1.0f);
            g_arrive[b] = 0;   // reset for graph replay
        }
    }
}

// ---------------- launch ----------------
extern "C" void kernel_launch(void* const* d_in, const int* in_sizes, int n_in,
                              void* d_out, int out_size) {
    const float* emb1 = (const float*)d_in[0];
    const float* emb2 = (const float*)d_in[1];
    const int*   mask1 = (const int*)d_in[2];
    const int*   mask2 = (const int*)d_in[3];
    float* out = (float*)d_out;

    cudaFuncSetAttribute(gemm_max_kernel,
                         cudaFuncAttributeMaxDynamicSharedMemorySize, SMEM_TOTAL);

    normalize_kernel<<<dim3(2048, 2), 256>>>(emb1, emb2);
    gemm_max_kernel<<<dim3(4, 4, B_), 256, SMEM_TOTAL>>>(mask1, mask2, out);
}

// round 6
// speedup vs baseline: 1.2445x; 1.0552x over previous
#include <cuda_runtime.h>
#include <cuda_bf16.h>
#include <cstdint>

#define B_   32
#define S_   512
#define D_   768
#define EPS_ 1e-8f

// ---------------- device scratch ----------------
__device__ __align__(16) __nv_bfloat16 g_n1[B_ * S_ * D_];
__device__ __align__(16) __nv_bfloat16 g_n2[B_ * S_ * D_];
__device__ unsigned g_rowmax[B_ * S_];   // order-preserving mapped fp32
__device__ unsigned g_colmax[B_ * S_];
__device__ int      g_arrive[B_];

// ---------------- helpers ----------------
__device__ __forceinline__ uint32_t smem_u32(const void* p) {
    uint32_t a;
    asm("{ .reg .u64 t; cvta.to.shared.u64 t, %1; cvt.u32.u64 %0, t; }" : "=r"(a) : "l"(p));
    return a;
}
__device__ __forceinline__ unsigned fmap(float x) {
    int i = __float_as_int(x);
    return (unsigned)(i ^ ((i >> 31) | 0x80000000));
}
__device__ __forceinline__ float fumap(unsigned u) {
    int i = (int)(u ^ ((u & 0x80000000u) ? 0x80000000u : 0xFFFFFFFFu));
    return __int_as_float(i);
}

#define CP_ASYNC16(dst, src) \
    asm volatile("cp.async.cg.shared.global [%0], [%1], 16;" :: "r"(dst), "l"(src))
#define CP_COMMIT() asm volatile("cp.async.commit_group;" ::: "memory")
#define CP_WAIT2()  asm volatile("cp.async.wait_group 2;" ::: "memory")
#define CP_WAIT1()  asm volatile("cp.async.wait_group 1;" ::: "memory")
#define CP_WAIT0()  asm volatile("cp.async.wait_group 0;" ::: "memory")

#define LDMATRIX_X4(r0, r1, r2, r3, addr) \
    asm volatile("ldmatrix.sync.aligned.m8n8.x4.shared.b16 {%0,%1,%2,%3}, [%4];" \
                 : "=r"(r0), "=r"(r1), "=r"(r2), "=r"(r3) : "r"(addr))

// ---------------- kernel 1: normalize (warp per row) + all inits ----------------
__global__ __launch_bounds__(256) void normalize_kernel(const float* __restrict__ e1,
                                                        const float* __restrict__ e2) {
    const int lane = threadIdx.x & 31;
    const int wrp  = threadIdx.x >> 5;
    const int row  = blockIdx.x * 8 + wrp;

    if (blockIdx.y == 0 && blockIdx.x < 64) {
        int t = blockIdx.x * 256 + threadIdx.x;   // covers exactly 16384
        g_rowmax[t] = 0u;                          // 0 < fmap(x) for all x
        g_colmax[t] = 0u;
        if (t < B_) g_arrive[t] = 0;
    }

    const float* src = (blockIdx.y ? e2 : e1) + (size_t)row * D_;
    __nv_bfloat16* dst = (blockIdx.y ? g_n2 : g_n1) + (size_t)row * D_;

    float4 v[6];
    float ss = 0.0f;
    #pragma unroll
    for (int k = 0; k < 6; k++) {
        v[k] = __ldcs((const float4*)(src + lane * 4 + k * 128));
        ss += v[k].x * v[k].x + v[k].y * v[k].y + v[k].z * v[k].z + v[k].w * v[k].w;
    }
    #pragma unroll
    for (int o = 16; o; o >>= 1) ss += __shfl_xor_sync(0xffffffffu, ss, o);

    const float s = 1.0f / fmaxf(sqrtf(ss), EPS_);

    #pragma unroll
    for (int k = 0; k < 6; k++) {
        *(__nv_bfloat162*)(dst + lane * 4 + k * 128)     = __floats2bfloat162_rn(v[k].x * s, v[k].y * s);
        *(__nv_bfloat162*)(dst + lane * 4 + k * 128 + 2) = __floats2bfloat162_rn(v[k].z * s, v[k].w * s);
    }
}

// ---------------- kernel 2: 4-stage pipelined HMMA GEMM, one barrier/chunk ------
// CTA tile 128x128, 8 warps 2(m)x4(n), warp tile 64x32, mma m16n8k16 bf16.
// KC=48 (16 chunks), pitch 112B (conflict-free ldmatrix), 4-stage cp.async ring.
#define KC     48
#define NCH    (D_ / KC)                 // 16
#define PITCH  112                       // bytes per row (56 bf16)
#define AT_BYTES (128 * PITCH)           // 14336
#define STAGE_BYTES (2 * AT_BYTES)       // 28672 (A + B)
#define SMEM_TOTAL (4 * STAGE_BYTES)     // 114688

__device__ __forceinline__ void load_chunk(uint32_t sA, uint32_t sB,
                                           const __nv_bfloat16* gA,
                                           const __nv_bfloat16* gB,
                                           int kk, int tid) {
    #pragma unroll
    for (int q = 0; q < 3; q++) {                 // A: 128 rows x 6 segs
        int idx = tid + q * 256;                  // 0..767
        int row = idx / 6, seg = idx % 6;
        CP_ASYNC16(sA + row * PITCH + seg * 16, gA + (size_t)row * D_ + kk + seg * 8);
    }
    #pragma unroll
    for (int q = 0; q < 3; q++) {                 // B
        int idx = tid + q * 256;
        int row = idx / 6, seg = idx % 6;
        CP_ASYNC16(sB + row * PITCH + seg * 16, gB + (size_t)row * D_ + kk + seg * 8);
    }
}

__global__ __launch_bounds__(256, 2) void gemm_max_kernel(const int* __restrict__ mask1,
                                                          const int* __restrict__ mask2,
                                                          float* __restrict__ out) {
    extern __shared__ char smem[];
    const uint32_t sbase = smem_u32(smem);

    const int tid  = threadIdx.x;
    const int lane = tid & 31;
    const int g    = lane >> 2;
    const int tg   = lane & 3;
    const int warp = tid >> 5;
    const int wm   = warp >> 2;
    const int wn   = warp & 3;

    const int b  = blockIdx.z;
    const int i0 = blockIdx.y * 128;
    const int j0 = blockIdx.x * 128;

    float c[4][4][4];
    #pragma unroll
    for (int mf = 0; mf < 4; mf++)
        #pragma unroll
        for (int nf = 0; nf < 4; nf++)
            #pragma unroll
            for (int e = 0; e < 4; e++) c[mf][nf][e] = 0.0f;

    const __nv_bfloat16* gA = g_n1 + (size_t)(b * S_ + i0) * D_;
    const __nv_bfloat16* gB = g_n2 + (size_t)(b * S_ + j0) * D_;

    uint32_t sA[4], sB[4];
    #pragma unroll
    for (int s = 0; s < 4; s++) {
        sA[s] = sbase + s * STAGE_BYTES;
        sB[s] = sbase + s * STAGE_BYTES + AT_BYTES;
    }

    const uint32_t aoff = (uint32_t)((wm * 64 + (lane & 15)) * PITCH + (lane >> 4) * 16);
    const uint32_t boff = (uint32_t)((wn * 32 + (lane & 7) + ((lane >> 4) << 3)) * PITCH
                                     + ((lane >> 3) & 1) * 16);

    // prologue: chunks 0,1 in flight
    load_chunk(sA[0], sB[0], gA, gB, 0,  tid); CP_COMMIT();
    load_chunk(sA[1], sB[1], gA, gB, KC, tid); CP_COMMIT();

    unsigned af[2][4][4], bfr[2][4][2];

    #pragma unroll 1
    for (int ch = 0; ch < NCH; ch++) {
        const int buf = ch & 3;

        // issue loads for chunk ch+2 into buf (ch+2)&3 == (ch-2)&3.
        // Safe pre-barrier: previous iteration's barrier proved all warps
        // finished computing chunk ch-2 (the last reader of that buffer).
        if (ch + 2 < NCH) {
            load_chunk(sA[(ch + 2) & 3], sB[(ch + 2) & 3], gA, gB, (ch + 2) * KC, tid);
            CP_COMMIT();
            CP_WAIT2();
        } else if (ch + 1 < NCH) {
            CP_WAIT1();
        } else {
            CP_WAIT0();
        }
        __syncthreads();     // chunk ch visible to all; all warps done with ch-1

        const uint32_t abase = sA[buf] + aoff;
        const uint32_t bbase = sB[buf] + boff;

        // preload ks=0 fragments
        #pragma unroll
        for (int mf = 0; mf < 4; mf++)
            LDMATRIX_X4(af[0][mf][0], af[0][mf][1], af[0][mf][2], af[0][mf][3],
                        abase + mf * 16 * PITCH);
        #pragma unroll
        for (int p = 0; p < 2; p++) {
            unsigned r0, r1, r2, r3;
            LDMATRIX_X4(r0, r1, r2, r3, bbase + p * 16 * PITCH);
            bfr[0][p * 2 + 0][0] = r0; bfr[0][p * 2 + 0][1] = r1;
            bfr[0][p * 2 + 1][0] = r2; bfr[0][p * 2 + 1][1] = r3;
        }

        #pragma unroll
        for (int ks = 0; ks < KC / 16; ks++) {     // 3 groups
            const int cur = ks & 1, nxt = cur ^ 1;
            if (ks + 1 < KC / 16) {
                const uint32_t kb2 = (ks + 1) * 32;
                #pragma unroll
                for (int mf = 0; mf < 4; mf++)
                    LDMATRIX_X4(af[nxt][mf][0], af[nxt][mf][1], af[nxt][mf][2], af[nxt][mf][3],
                                abase + mf * 16 * PITCH + kb2);
                #pragma unroll
                for (int p = 0; p < 2; p++) {
                    unsigned r0, r1, r2, r3;
                    LDMATRIX_X4(r0, r1, r2, r3, bbase + p * 16 * PITCH + kb2);
                    bfr[nxt][p * 2 + 0][0] = r0; bfr[nxt][p * 2 + 0][1] = r1;
                    bfr[nxt][p * 2 + 1][0] = r2; bfr[nxt][p * 2 + 1][1] = r3;
                }
            }
            #pragma unroll
            for (int mf = 0; mf < 4; mf++)
                #pragma unroll
                for (int nf = 0; nf < 4; nf++)
                    asm volatile(
                        "mma.sync.aligned.m16n8k16.row.col.f32.bf16.bf16.f32 "
                        "{%0,%1,%2,%3},{%4,%5,%6,%7},{%8,%9},{%0,%1,%2,%3};"
                        : "+f"(c[mf][nf][0]), "+f"(c[mf][nf][1]),
                          "+f"(c[mf][nf][2]), "+f"(c[mf][nf][3])
                        : "r"(af[cur][mf][0]), "r"(af[cur][mf][1]),
                          "r"(af[cur][mf][2]), "r"(af[cur][mf][3]),
                          "r"(bfr[cur][nf][0]), "r"(bfr[cur][nf][1]));
        }
    }

    // -------- fused masked max epilogue --------
    const int baseRow = b * S_ + i0 + wm * 64;
    const int baseCol = b * S_ + j0 + wn * 32;

    int m1v[4][2], m2v[4][2];
    #pragma unroll
    for (int mf = 0; mf < 4; mf++) {
        m1v[mf][0] = mask1[baseRow + mf * 16 + g];
        m1v[mf][1] = mask1[baseRow + mf * 16 + g + 8];
    }
    #pragma unroll
    for (int nf = 0; nf < 4; nf++) {
        m2v[nf][0] = mask2[baseCol + nf * 8 + 2 * tg];
        m2v[nf][1] = mask2[baseCol + nf * 8 + 2 * tg + 1];
    }

    #pragma unroll
    for (int mf = 0; mf < 4; mf++)
        #pragma unroll
        for (int y = 0; y < 2; y++) {
            float r = -INFINITY;
            #pragma unroll
            for (int nf = 0; nf < 4; nf++) {
                if (m2v[nf][0]) r = fmaxf(r, c[mf][nf][y * 2 + 0]);
                if (m2v[nf][1]) r = fmaxf(r, c[mf][nf][y * 2 + 1]);
            }
            r = fmaxf(r, __shfl_xor_sync(0xffffffffu, r, 1));
            r = fmaxf(r, __shfl_xor_sync(0xffffffffu, r, 2));
            if (tg == 0)
                atomicMax(&g_rowmax[baseRow + mf * 16 + g + 8 * y], fmap(r));
        }

    #pragma unroll
    for (int nf = 0; nf < 4; nf++)
        #pragma unroll
        for (int x = 0; x < 2; x++) {
            float cm = -INFINITY;
            #pragma unroll
            for (int mf = 0; mf < 4; mf++) {
                if (m1v[mf][0]) cm = fmaxf(cm, c[mf][nf][0 * 2 + x]);
                if (m1v[mf][1]) cm = fmaxf(cm, c[mf][nf][1 * 2 + x]);
            }
            cm = fmaxf(cm, __shfl_xor_sync(0xffffffffu, cm, 4));
            cm = fmaxf(cm, __shfl_xor_sync(0xffffffffu, cm, 8));
            cm = fmaxf(cm, __shfl_xor_sync(0xffffffffu, cm, 16));
            if (g == 0)
                atomicMax(&g_colmax[baseCol + nf * 8 + 2 * tg + x], fmap(cm));
        }

    // -------- fused finalize: 16th-arriving CTA per batch computes score --------
    __shared__ float fsum[8];
    __shared__ int   fcnt[8];
    __shared__ int   s_old;

    __threadfence();
    if (tid == 0) s_old = atomicAdd(&g_arrive[b], 1);
    __syncthreads();
    if (s_old == 15) {
        __threadfence();
        float sum = 0.0f;
        int cnt = 0;
        for (int j = tid; j < S_; j += 256) {
            int a1 = mask1[b * S_ + j];
            int a2 = mask2[b * S_ + j];
            cnt += a1 + a2;
            if (a1) sum += fumap(__ldcg(&g_rowmax[b * S_ + j]));
            if (a2) sum += fumap(__ldcg(&g_colmax[b * S_ + j]));
        }
        #pragma unroll
        for (int o = 16; o; o >>= 1) {
            sum += __shfl_xor_sync(0xffffffffu, sum, o);
            cnt += __shfl_xor_sync(0xffffffffu, cnt, o);
        }
        if (lane == 0) { fsum[warp] = sum; fcnt[warp] = cnt; }
        __syncthreads();
        if (tid == 0) {
            float ts = 0.f; int tc = 0;
            #pragma unroll
            for (int i = 0; i < 8; i++) { ts += fsum[i]; tc += fcnt[i]; }
            out[b] = ts / fmaxf((float)tc, 1.0f);
            g_arrive[b] = 0;   // reset for graph replay
        }
    }
}

// ---------------- launch ----------------
extern "C" void kernel_launch(void* const* d_in, const int* in_sizes, int n_in,
                              void* d_out, int out_size) {
    const float* emb1 = (const float*)d_in[0];
    const float* emb2 = (const float*)d_in[1];
    const int*   mask1 = (const int*)d_in[2];
    const int*   mask2 = (const int*)d_in[3];
    float* out = (float*)d_out;

    cudaFuncSetAttribute(gemm_max_kernel,
                         cudaFuncAttributeMaxDynamicSharedMemorySize, SMEM_TOTAL);

    normalize_kernel<<<dim3(2048, 2), 256>>>(emb1, emb2);
    gemm_max_kernel<<<dim3(4, 4, B_), 256, SMEM_TOTAL>>>(mask1, mask2, out);
}

// round 7
// speedup vs baseline: 1.4003x; 1.1252x over previous
#include <cuda_runtime.h>
#include <cuda_bf16.h>
#include <cstdint>

#define B_   32
#define S_   512
#define D_   768
#define EPS_ 1e-8f

#define KC    64
#define NCH   (D_ / KC)          // 12

// ---------------- device scratch (chunk-tiled, pre-swizzled bf16) ----------------
// layout: [b][kc][row][64 bf16], 128B per row, swizzle XOR (row&7)<<4 applied on col bytes
__device__ __align__(16) __nv_bfloat16 g_n1t[B_ * S_ * D_];
__device__ __align__(16) __nv_bfloat16 g_n2t[B_ * S_ * D_];
__device__ unsigned g_rowmax[B_ * S_];   // order-preserving mapped fp32
__device__ unsigned g_colmax[B_ * S_];
__device__ int      g_arrive[B_];

// ---------------- helpers ----------------
__device__ __forceinline__ uint32_t smem_u32(const void* p) {
    uint32_t a;
    asm("{ .reg .u64 t; cvta.to.shared.u64 t, %1; cvt.u32.u64 %0, t; }" : "=r"(a) : "l"(p));
    return a;
}
__device__ __forceinline__ unsigned fmap(float x) {
    int i = __float_as_int(x);
    return (unsigned)(i ^ ((i >> 31) | 0x80000000));
}
__device__ __forceinline__ float fumap(unsigned u) {
    int i = (int)(u ^ ((u & 0x80000000u) ? 0x80000000u : 0xFFFFFFFFu));
    return __int_as_float(i);
}

#define MBARRIER_INIT(addr, cnt) \
    asm volatile("mbarrier.init.shared.b64 [%0], %1;" :: "r"(addr), "r"(cnt) : "memory")
#define MBARRIER_EXPECT_TX(addr, bytes) \
    asm volatile("mbarrier.arrive.expect_tx.shared.b64 _, [%0], %1;" :: "r"(addr), "r"(bytes) : "memory")
#define MBARRIER_WAIT_PARITY(mbar_addr, phase_parity) do {                          \
    uint32_t _mbar = (uint32_t)(mbar_addr);                                         \
    uint32_t _par  = (uint32_t)(phase_parity);                                      \
    asm volatile(                                                                   \
        "{\n\t.reg .pred P1;\n\t"                                                   \
        "WAIT_LOOP_%=:\n\t"                                                         \
        "mbarrier.try_wait.parity.acquire.cta.shared::cta.b64 P1, [%0], %1, 0x989680;\n\t" \
        "@P1 bra.uni WAIT_DONE_%=;\n\t"                                             \
        "bra.uni WAIT_LOOP_%=;\n\t"                                                 \
        "WAIT_DONE_%=:\n\t}"                                                        \
        :: "r"(_mbar), "r"(_par) : "memory");                                       \
} while (0)

#define BULK_LOAD(dst, src, size, mbar) \
    asm volatile("cp.async.bulk.shared::cluster.global.mbarrier::complete_tx::bytes " \
                 "[%0], [%1], %2, [%3];" \
                 :: "r"(dst), "l"(src), "r"(size), "r"(mbar) : "memory")

#define LDMATRIX_X4(r0, r1, r2, r3, addr) \
    asm volatile("ldmatrix.sync.aligned.m8n8.x4.shared.b16 {%0,%1,%2,%3}, [%4];" \
                 : "=r"(r0), "=r"(r1), "=r"(r2), "=r"(r3) : "r"(addr))

// ---------------- kernel 1: normalize (warp per row) -> tiled swizzled layout ----
__global__ __launch_bounds__(256) void normalize_kernel(const float* __restrict__ e1,
                                                        const float* __restrict__ e2) {
    const int lane = threadIdx.x & 31;
    const int wrp  = threadIdx.x >> 5;
    const int grow = blockIdx.x * 8 + wrp;      // 0..16383
    const int b    = grow >> 9;
    const int r    = grow & 511;

    if (blockIdx.y == 0 && blockIdx.x < 64) {
        int t = blockIdx.x * 256 + threadIdx.x;   // covers exactly 16384
        g_rowmax[t] = 0u;                          // 0 < fmap(x) for all x
        g_colmax[t] = 0u;
        if (t < B_) g_arrive[t] = 0;
    }

    const float* src = (blockIdx.y ? e2 : e1) + (size_t)grow * D_;
    __nv_bfloat16* dstBase = blockIdx.y ? g_n2t : g_n1t;

    float4 v[6];
    float ss = 0.0f;
    #pragma unroll
    for (int k = 0; k < 6; k++) {
        v[k] = __ldcs((const float4*)(src + lane * 4 + k * 128));
        ss += v[k].x * v[k].x + v[k].y * v[k].y + v[k].z * v[k].z + v[k].w * v[k].w;
    }
    #pragma unroll
    for (int o = 16; o; o >>= 1) ss += __shfl_xor_sync(0xffffffffu, ss, o);

    const float s = 1.0f / fmaxf(sqrtf(ss), EPS_);
    const int swz = (r & 7) << 3;                 // bf16-unit swizzle within 64-col row

    #pragma unroll
    for (int k = 0; k < 6; k++) {
        int cg = lane * 4 + k * 128;              // global col 0..767
        int kc = cg >> 6;
        int c  = cg & 63;
        size_t idx = ((size_t)(b * NCH + kc) * S_ + r) * 64 + (size_t)(c ^ swz);
        *(__nv_bfloat162*)(dstBase + idx)     = __floats2bfloat162_rn(v[k].x * s, v[k].y * s);
        *(__nv_bfloat162*)(dstBase + idx + 2) = __floats2bfloat162_rn(v[k].z * s, v[k].w * s);
    }
}

// ---------------- kernel 2: bulk-copy pipelined HMMA GEMM ----------------
// CTA tile 128x128, 8 warps 2(m)x4(n), warp tile 64x32, mma m16n8k16 bf16.
// Fill: cp.async.bulk 16KB x2 per chunk (thread 0), 3-stage mbarrier ring.
#define TILE_BYTES  16384                 // 128 rows x 128B
#define STAGE_BYTES (2 * TILE_BYTES)      // A + B
#define SM_BUF      1024
#define SMEM_TOTAL  (SM_BUF + 3 * STAGE_BYTES)   // 99328

__global__ __launch_bounds__(256, 2) void gemm_max_kernel(const int* __restrict__ mask1,
                                                          const int* __restrict__ mask2,
                                                          float* __restrict__ out) {
    extern __shared__ char smem[];
    const uint32_t sbase = smem_u32(smem);

    const int tid  = threadIdx.x;
    const int lane = tid & 31;
    const int g    = lane >> 2;
    const int tg   = lane & 3;
    const int warp = tid >> 5;
    const int wm   = warp >> 2;
    const int wn   = warp & 3;

    const int b  = blockIdx.z;
    const int i0 = blockIdx.y * 128;
    const int j0 = blockIdx.x * 128;

    float c[4][4][4];
    #pragma unroll
    for (int mf = 0; mf < 4; mf++)
        #pragma unroll
        for (int nf = 0; nf < 4; nf++)
            #pragma unroll
            for (int e = 0; e < 4; e++) c[mf][nf][e] = 0.0f;

    uint32_t mb[3], sA[3], sB[3];
    #pragma unroll
    for (int s = 0; s < 3; s++) {
        mb[s] = sbase + s * 8;
        sA[s] = sbase + SM_BUF + s * STAGE_BYTES;
        sB[s] = sA[s] + TILE_BYTES;
    }

    if (tid == 0) {
        MBARRIER_INIT(mb[0], 1);
        MBARRIER_INIT(mb[1], 1);
        MBARRIER_INIT(mb[2], 1);
    }
    __syncthreads();

    // gmem chunk bases (16KB contiguous per chunk)
    const __nv_bfloat16* gA0 = g_n1t + ((size_t)(b * NCH) * S_ + i0) * 64;
    const __nv_bfloat16* gB0 = g_n2t + ((size_t)(b * NCH) * S_ + j0) * 64;
    const size_t CH_STRIDE = (size_t)S_ * 64;     // elements per chunk step

    if (tid == 0) {
        #pragma unroll
        for (int p = 0; p < 2; p++) {
            MBARRIER_EXPECT_TX(mb[p], STAGE_BYTES);
            BULK_LOAD(sA[p], gA0 + p * CH_STRIDE, TILE_BYTES, mb[p]);
            BULK_LOAD(sB[p], gB0 + p * CH_STRIDE, TILE_BYTES, mb[p]);
        }
    }

    // per-lane ldmatrix addressing (swizzled 128B-pitch rows)
    const int ar = wm * 64 + (lane & 15);
    const uint32_t arow = (uint32_t)ar * 128;
    const uint32_t aswz = (uint32_t)(ar & 7) << 4;
    const uint32_t ac0  = (uint32_t)(lane >> 4) * 16;

    const int br = wn * 32 + (lane & 7) + ((lane >> 4) << 3);
    const uint32_t brow = (uint32_t)br * 128;
    const uint32_t bswz = (uint32_t)(br & 7) << 4;
    const uint32_t bc0  = (uint32_t)((lane >> 3) & 1) * 16;

    unsigned af[2][4][4], bfr[2][4][2];

    #pragma unroll 1
    for (int ch = 0; ch < NCH; ch++) {
        const int stage = ch % 3;

        __syncthreads();    // all warps finished computing chunk ch-1
        if (tid == 0 && ch + 2 < NCH) {
            const int s2 = (ch + 2) % 3;
            MBARRIER_EXPECT_TX(mb[s2], STAGE_BYTES);
            BULK_LOAD(sA[s2], gA0 + (size_t)(ch + 2) * CH_STRIDE, TILE_BYTES, mb[s2]);
            BULK_LOAD(sB[s2], gB0 + (size_t)(ch + 2) * CH_STRIDE, TILE_BYTES, mb[s2]);
        }
        MBARRIER_WAIT_PARITY(mb[stage], (ch / 3) & 1);

        const uint32_t abase = sA[stage] + arow;
        const uint32_t bbase = sB[stage] + brow;

        // preload ks=0 fragments
        #pragma unroll
        for (int mf = 0; mf < 4; mf++)
            LDMATRIX_X4(af[0][mf][0], af[0][mf][1], af[0][mf][2], af[0][mf][3],
                        abase + mf * 2048 + (ac0 ^ aswz));
        #pragma unroll
        for (int p = 0; p < 2; p++) {
            unsigned r0, r1, r2, r3;
            LDMATRIX_X4(r0, r1, r2, r3, bbase + p * 2048 + (bc0 ^ bswz));
            bfr[0][p * 2 + 0][0] = r0; bfr[0][p * 2 + 0][1] = r1;
            bfr[0][p * 2 + 1][0] = r2; bfr[0][p * 2 + 1][1] = r3;
        }

        #pragma unroll
        for (int ks = 0; ks < KC / 16; ks++) {     // 4 groups
            const int cur = ks & 1, nxt = cur ^ 1;
            if (ks + 1 < KC / 16) {
                const uint32_t kb2 = (uint32_t)(ks + 1) * 32;
                #pragma unroll
                for (int mf = 0; mf < 4; mf++)
                    LDMATRIX_X4(af[nxt][mf][0], af[nxt][mf][1], af[nxt][mf][2], af[nxt][mf][3],
                                abase + mf * 2048 + ((ac0 + kb2) ^ aswz));
                #pragma unroll
                for (int p = 0; p < 2; p++) {
                    unsigned r0, r1, r2, r3;
                    LDMATRIX_X4(r0, r1, r2, r3, bbase + p * 2048 + ((bc0 + kb2) ^ bswz));
                    bfr[nxt][p * 2 + 0][0] = r0; bfr[nxt][p * 2 + 0][1] = r1;
                    bfr[nxt][p * 2 + 1][0] = r2; bfr[nxt][p * 2 + 1][1] = r3;
                }
            }
            #pragma unroll
            for (int mf = 0; mf < 4; mf++)
                #pragma unroll
                for (int nf = 0; nf < 4; nf++)
                    asm volatile(
                        "mma.sync.aligned.m16n8k16.row.col.f32.bf16.bf16.f32 "
                        "{%0,%1,%2,%3},{%4,%5,%6,%7},{%8,%9},{%0,%1,%2,%3};"
                        : "+f"(c[mf][nf][0]), "+f"(c[mf][nf][1]),
                          "+f"(c[mf][nf][2]), "+f"(c[mf][nf][3])
                        : "r"(af[cur][mf][0]), "r"(af[cur][mf][1]),
                          "r"(af[cur][mf][2]), "r"(af[cur][mf][3]),
                          "r"(bfr[cur][nf][0]), "r"(bfr[cur][nf][1]));
        }
    }

    // -------- fused masked max epilogue --------
    const int baseRow = b * S_ + i0 + wm * 64;
    const int baseCol = b * S_ + j0 + wn * 32;

    int m1v[4][2], m2v[4][2];
    #pragma unroll
    for (int mf = 0; mf < 4; mf++) {
        m1v[mf][0] = mask1[baseRow + mf * 16 + g];
        m1v[mf][1] = mask1[baseRow + mf * 16 + g + 8];
    }
    #pragma unroll
    for (int nf = 0; nf < 4; nf++) {
        m2v[nf][0] = mask2[baseCol + nf * 8 + 2 * tg];
        m2v[nf][1] = mask2[baseCol + nf * 8 + 2 * tg + 1];
    }

    #pragma unroll
    for (int mf = 0; mf < 4; mf++)
        #pragma unroll
        for (int y = 0; y < 2; y++) {
            float r = -INFINITY;
            #pragma unroll
            for (int nf = 0; nf < 4; nf++) {
                if (m2v[nf][0]) r = fmaxf(r, c[mf][nf][y * 2 + 0]);
                if (m2v[nf][1]) r = fmaxf(r, c[mf][nf][y * 2 + 1]);
            }
            r = fmaxf(r, __shfl_xor_sync(0xffffffffu, r, 1));
            r = fmaxf(r, __shfl_xor_sync(0xffffffffu, r, 2));
            if (tg == 0)
                atomicMax(&g_rowmax[baseRow + mf * 16 + g + 8 * y], fmap(r));
        }

    #pragma unroll
    for (int nf = 0; nf < 4; nf++)
        #pragma unroll
        for (int x = 0; x < 2; x++) {
            float cm = -INFINITY;
            #pragma unroll
            for (int mf = 0; mf < 4; mf++) {
                if (m1v[mf][0]) cm = fmaxf(cm, c[mf][nf][0 * 2 + x]);
                if (m1v[mf][1]) cm = fmaxf(cm, c[mf][nf][1 * 2 + x]);
            }
            cm = fmaxf(cm, __shfl_xor_sync(0xffffffffu, cm, 4));
            cm = fmaxf(cm, __shfl_xor_sync(0xffffffffu, cm, 8));
            cm = fmaxf(cm, __shfl_xor_sync(0xffffffffu, cm, 16));
            if (g == 0)
                atomicMax(&g_colmax[baseCol + nf * 8 + 2 * tg + x], fmap(cm));
        }

    // -------- fused finalize: 16th-arriving CTA per batch computes score --------
    __shared__ float fsum[8];
    __shared__ int   fcnt[8];
    __shared__ int   s_old;

    __threadfence();
    if (tid == 0) s_old = atomicAdd(&g_arrive[b], 1);
    __syncthreads();
    if (s_old == 15) {
        __threadfence();
        float sum = 0.0f;
        int cnt = 0;
        for (int j = tid; j < S_; j += 256) {
            int a1 = mask1[b * S_ + j];
            int a2 = mask2[b * S_ + j];
            cnt += a1 + a2;
            if (a1) sum += fumap(__ldcg(&g_rowmax[b * S_ + j]));
            if (a2) sum += fumap(__ldcg(&g_colmax[b * S_ + j]));
        }
        #pragma unroll
        for (int o = 16; o; o >>= 1) {
            sum += __shfl_xor_sync(0xffffffffu, sum, o);
            cnt += __shfl_xor_sync(0xffffffffu, cnt, o);
        }
        if (lane == 0) { fsum[warp] = sum; fcnt[warp] = cnt; }
        __syncthreads();
        if (tid == 0) {
            float ts = 0.f; int tc = 0;
            #pragma unroll
            for (int i = 0; i < 8; i++) { ts += fsum[i]; tc += fcnt[i]; }
            out[b] = ts / fmaxf((float)tc, 1.0f);
            g_arrive[b] = 0;   // reset for graph replay
        }
    }
}

// ---------------- launch ----------------
extern "C" void kernel_launch(void* const* d_in, const int* in_sizes, int n_in,
                              void* d_out, int out_size) {
    const float* emb1 = (const float*)d_in[0];
    const float* emb2 = (const float*)d_in[1];
    const int*   mask1 = (const int*)d_in[2];
    const int*   mask2 = (const int*)d_in[3];
    float* out = (float*)d_out;

    cudaFuncSetAttribute(gemm_max_kernel,
                         cudaFuncAttributeMaxDynamicSharedMemorySize, SMEM_TOTAL);

    normalize_kernel<<<dim3(2048, 2), 256>>>(emb1, emb2);
    gemm_max_kernel<<<dim3(4, 4, B_), 256, SMEM_TOTAL>>>(mask1, mask2, out);
}